// round 5
// baseline (speedup 1.0000x reference)
#include <cuda_runtime.h>
#include <string.h>

// ---------------- problem constants ----------------
#define N_TOK   32768       // B*H*W = 32*32*32
#define K_CODE  8192
#define D_DIM   64
#define ZQ_ELEMS 2097152    // 32*64*32*32

// output layout (concat of reference returns, float32)
#define ZQ_OFF   0
#define LOSS_OFF 2097152
#define IDX_OFF  2097153
#define CSN_OFF  (2097153 + 32768)            // 2129921
#define EMA_OFF  (2129921 + 8192)             // 2138113
#define EMB_OFF  (2138113 + 524288)           // 2662401

#define DECAYF   0.99f
#define OMDF     0.00999999977648258209228515625f  // f32(1.0 - 0.99)
#define EPSF     1e-5f
#define KEPSF    0.08192f                          // f32(8192 * 1e-5)
#define BETAF    0.25f

// ---------------- device scratch (no allocation allowed) ----------------
__device__ float2             g_zpack[32u * 32768u];   // [s][n]  d-pair-major z
__device__ float2             g_epack[32u * 8192u];    // [s][k]  d-pair-major emb
__device__ float              g_bias[K_CODE];          // 0.5*||e_k||^2
__device__ unsigned long long g_keys[N_TOK];
__device__ int                g_idx[N_TOK];
__device__ int                g_counts[K_CODE];
__device__ float              g_sumw[K_CODE * D_DIM];
__device__ float              g_cs[K_CODE];
__device__ float              g_cssum;
__device__ float              g_loss;

// ---------------- helpers ----------------
__device__ __forceinline__ unsigned long long pack2(float x, float y) {
    float2 t = make_float2(x, y);
    unsigned long long r;
    memcpy(&r, &t, 8);
    return r;
}
__device__ __forceinline__ float2 unpack2(unsigned long long v) {
    float2 t;
    memcpy(&t, &v, 8);
    return t;
}
__device__ __forceinline__ unsigned orderf(float f) {
    unsigned u = __float_as_uint(f);
    return (u & 0x80000000u) ? ~u : (u | 0x80000000u);
}
__device__ __forceinline__ void cp16(void* dst, const void* src) {
    unsigned sa = (unsigned)__cvta_generic_to_shared(dst);
    asm volatile("cp.async.cg.shared.global [%0], [%1], 16;" :: "r"(sa), "l"(src));
}
__device__ __forceinline__ void block_atomic_add(float v, float* target) {
    #pragma unroll
    for (int m = 16; m >= 1; m >>= 1) v += __shfl_xor_sync(0xffffffffu, v, m);
    __shared__ float red[8];
    int w = threadIdx.x >> 5;
    if ((threadIdx.x & 31) == 0) red[w] = v;
    __syncthreads();
    if (threadIdx.x == 0) {
        float s = 0.f;
        #pragma unroll
        for (int i = 0; i < 8; i++) s += red[i];
        atomicAdd(target, s);
    }
}

// ---------------- K0: zero scratch ----------------
__global__ void k_zero() {
    int gid = blockIdx.x * 256 + threadIdx.x;   // 524288 threads
    g_sumw[gid] = 0.f;
    if (gid < N_TOK)  g_keys[gid]   = 0ull;
    if (gid < K_CODE) g_counts[gid] = 0;
    if (gid == 0) { g_cssum = 0.f; g_loss = 0.f; }
}

// ---------------- Kp: pack codebook + half-norms ----------------
__global__ void k_epack(const float* __restrict__ emb) {
    int k = blockIdx.x * 256 + threadIdx.x;     // 8192 threads
    const float4* ep = reinterpret_cast<const float4*>(emb + (size_t)k * D_DIM);
    float nrm = 0.f;
    #pragma unroll
    for (int s4 = 0; s4 < 16; s4++) {
        float4 v = ep[s4];
        nrm += v.x * v.x + v.y * v.y + v.z * v.z + v.w * v.w;
        g_epack[(2 * s4)     * K_CODE + k] = make_float2(v.x, v.y);
        g_epack[(2 * s4 + 1) * K_CODE + k] = make_float2(v.z, v.w);
    }
    g_bias[k] = 0.5f * nrm;
}

// ---------------- Kt: transpose/pack z (NCHW -> [s][n] float2) ----------------
__global__ void k_zpack(const float* __restrict__ z) {
    int gid = blockIdx.x * 256 + threadIdx.x;   // 1048576 threads
    int s = gid >> 15;
    int n = gid & 32767;
    int b = n >> 10, hw = n & 1023;
    const float* zp = z + (size_t)b * 65536 + (size_t)(2 * s) * 1024 + hw;
    g_zpack[s * 32768 + n] = make_float2(zp[0], zp[1024]);
}

// ---------------- K2: main fused GEMM + argmax, f32x2 packed FMA ----------------
// grid 2048 = 512 token tiles (64 tokens) x 4 K-splits; 256 threads;
// 80KB dyn smem, 2 CTAs/SM (4 warps/SMSP) for latency hiding.
// Thread tile: 4 tokens x 8 codes (f32x2-packed along d).
__global__ void __launch_bounds__(256, 2) k_main() {
    extern __shared__ float2 smem[];
    float2* Zs = smem;            // [32][64]
    float2* Es = smem + 2048;     // double buffer [2][32][128]

    const int tid = threadIdx.x;
    const int tx = tid & 15, ty = tid >> 4;
    const int tile_m = blockIdx.x & 511;
    const int ks = blockIdx.x >> 9;
    const int m0 = tile_m << 6;   // 64 tokens per block
    const int c0 = ks << 11;      // 2048 codes per K-split

    // load Z tile (stays for whole kernel): 32x64 float2 = 1024 float4
    #pragma unroll
    for (int r = 0; r < 4; r++) {
        int q = tid + (r << 8);
        int s = q >> 5, c4 = q & 31;
        *reinterpret_cast<float4*>(&Zs[s * 64 + c4 * 2]) =
            *reinterpret_cast<const float4*>(&g_zpack[s * 32768 + m0 + c4 * 2]);
    }
    // prologue: E tile 0 (32x128 float2 = 2048 float4)
    #pragma unroll
    for (int r = 0; r < 8; r++) {
        int q = tid + (r << 8);
        int s = q >> 6, c4 = q & 63;
        cp16(&Es[s * 128 + c4 * 2], &g_epack[s * 8192 + c0 + c4 * 2]);
    }
    asm volatile("cp.async.commit_group;");

    float bs[4]; int bi[4];
    #pragma unroll
    for (int i = 0; i < 4; i++) { bs[i] = -3.4e38f; bi[i] = 0; }

    for (int t = 0; t < 16; ++t) {
        const int buf = t & 1;
        if (t + 1 < 16) {
            int nb = (t + 1) & 1;
            int cb = c0 + ((t + 1) << 7);
            #pragma unroll
            for (int r = 0; r < 8; r++) {
                int q = tid + (r << 8);
                int s = q >> 6, c4 = q & 63;
                cp16(&Es[nb * 4096 + s * 128 + c4 * 2], &g_epack[s * 8192 + cb + c4 * 2]);
            }
            asm volatile("cp.async.commit_group;");
            asm volatile("cp.async.wait_group 1;");
        } else {
            asm volatile("cp.async.wait_group 0;");
        }
        __syncthreads();

        const int cb = c0 + (t << 7);
        unsigned long long acc[4][8];
        #pragma unroll
        for (int j = 0; j < 8; j++) {
            float b = __ldg(&g_bias[cb + tx + (j << 4)]);
            unsigned long long iv = pack2(-b, 0.0f);   // fold -0.5||e||^2 into acc
            #pragma unroll
            for (int i = 0; i < 4; i++) acc[i][j] = iv;
        }
        const float2* Eb = Es + buf * 4096;
        #pragma unroll 1
        for (int s = 0; s < 32; ++s) {
            unsigned long long zr[4], er[8];
            #pragma unroll
            for (int i = 0; i < 4; i++)
                zr[i] = *reinterpret_cast<const unsigned long long*>(&Zs[s * 64 + ty + (i << 4)]);
            #pragma unroll
            for (int j = 0; j < 8; j++)
                er[j] = *reinterpret_cast<const unsigned long long*>(&Eb[s * 128 + tx + (j << 4)]);
            #pragma unroll
            for (int i = 0; i < 4; i++)
                #pragma unroll
                for (int j = 0; j < 8; j++)
                    asm("fma.rn.f32x2 %0, %1, %2, %0;" : "+l"(acc[i][j]) : "l"(zr[i]), "l"(er[j]));
        }
        #pragma unroll
        for (int i = 0; i < 4; i++)
            #pragma unroll
            for (int j = 0; j < 8; j++) {
                float2 v = unpack2(acc[i][j]);
                float sc = v.x + v.y;                 // score = dot - 0.5||e||^2
                int code = cb + tx + (j << 4);
                if (sc > bs[i]) { bs[i] = sc; bi[i] = code; }  // strict > keeps first
            }
        __syncthreads();
    }

    // reduce over the 16 tx-lanes sharing each token, then merge across K-splits
    #pragma unroll
    for (int i = 0; i < 4; i++) {
        float s = bs[i]; int c = bi[i];
        #pragma unroll
        for (int m = 8; m >= 1; m >>= 1) {
            float os = __shfl_xor_sync(0xffffffffu, s, m);
            int   oc = __shfl_xor_sync(0xffffffffu, c, m);
            if (os > s || (os == s && oc < c)) { s = os; c = oc; }
        }
        if (tx == 0) {
            int token = m0 + ty + (i << 4);
            unsigned long long key =
                ((unsigned long long)orderf(s) << 32) | (unsigned)(8191 - c);
            atomicMax(&g_keys[token], key);
        }
    }
}

// ---------------- K2b: decode argmax, counts + segment-sum of z ----------------
__global__ void k_finalize(float* __restrict__ out) {
    int n = blockIdx.x * 256 + threadIdx.x;     // 32768 threads
    unsigned long long key = g_keys[n];
    int code = 8191 - (int)(unsigned)(key & 0xffffffffu);
    g_idx[n] = code;
    out[IDX_OFF + n] = (float)code;
    atomicAdd(&g_counts[code], 1);
    float* sw = g_sumw + (size_t)code * D_DIM;
    #pragma unroll
    for (int s = 0; s < 32; s++) {
        float2 v = g_zpack[s * 32768 + n];
        atomicAdd(&sw[2 * s],     v.x);
        atomicAdd(&sw[2 * s + 1], v.y);
    }
}

// ---------------- K3: gather z_q (NCHW) + commitment-loss reduction ----------------
__global__ void k_gather(const float* __restrict__ z, const float* __restrict__ emb,
                         float* __restrict__ out) {
    int gid = blockIdx.x * 256 + threadIdx.x;   // 2097152 threads
    int b = gid >> 16, c = (gid >> 10) & 63, hw = gid & 1023;
    int n = (b << 10) | hw;
    int code = g_idx[n];
    float q  = __ldg(&emb[(size_t)code * D_DIM + c]);
    float zv = z[gid];
    float d  = q - zv;
    out[ZQ_OFF + gid] = zv + d;                 // straight-through: z + (zq - z)
    block_atomic_add(d * d, &g_loss);
}

// ---------------- K4a: cs = decay*cs_in + (1-decay)*counts ; sum ----------------
__global__ void k_cs(const float* __restrict__ cs_in) {
    int k = blockIdx.x * 256 + threadIdx.x;     // 8192 threads
    float c = DECAYF * cs_in[k] + OMDF * (float)g_counts[k];
    g_cs[k] = c;
    block_atomic_add(c, &g_cssum);
}

// ---------------- K4b: cs_norm, ema_w_out, emb_out, loss write ----------------
__global__ void k_out(const float* __restrict__ ema_w, float* __restrict__ out) {
    int gid = blockIdx.x * 256 + threadIdx.x;   // 524288 threads
    int k = gid >> 6, d = gid & 63;
    float denom = g_cssum + KEPSF;
    float cn = (g_cs[k] + EPSF) / denom;
    float ew = DECAYF * ema_w[gid] + OMDF * g_sumw[gid];
    out[EMA_OFF + gid] = ew;
    out[EMB_OFF + gid] = ew / cn;
    if (d == 0)   out[CSN_OFF + k] = cn;
    if (gid == 0) out[LOSS_OFF] = BETAF * g_loss * (1.0f / 2097152.0f);
}

// ---------------- launch ----------------
extern "C" void kernel_launch(void* const* d_in, const int* in_sizes, int n_in,
                              void* d_out, int out_size) {
    const float* z      = (const float*)d_in[0];
    const float* emb    = (const float*)d_in[1];
    const float* ema_w  = (const float*)d_in[2];
    const float* cs_in  = (const float*)d_in[3];
    float* out = (float*)d_out;

    cudaFuncSetAttribute(k_main, cudaFuncAttributeMaxDynamicSharedMemorySize, 81920);

    k_zero    <<<2048, 256>>>();
    k_epack   <<<  32, 256>>>(emb);
    k_zpack   <<<4096, 256>>>(z);
    k_main    <<<2048, 256, 81920>>>();
    k_finalize<<< 128, 256>>>(out);
    k_gather  <<<8192, 256>>>(z, emb, out);
    k_cs      <<<  32, 256>>>(cs_in);
    k_out     <<<2048, 256>>>(ema_w, out);
}

// round 7
// speedup vs baseline: 1.0444x; 1.0444x over previous
#include <cuda_runtime.h>
#include <string.h>

// ---------------- problem constants ----------------
#define N_TOK   32768       // B*H*W = 32*32*32
#define K_CODE  8192
#define D_DIM   64
#define ZQ_ELEMS 2097152    // 32*64*32*32

// output layout (concat of reference returns, float32)
#define ZQ_OFF   0
#define LOSS_OFF 2097152
#define IDX_OFF  2097153
#define CSN_OFF  (2097153 + 32768)            // 2129921
#define EMA_OFF  (2129921 + 8192)             // 2138113
#define EMB_OFF  (2138113 + 524288)           // 2662401

#define DECAYF   0.99f
#define OMDF     0.00999999977648258209228515625f  // f32(1.0 - 0.99)
#define EPSF     1e-5f
#define KEPSF    0.08192f                          // f32(8192 * 1e-5)
#define BETAF    0.25f

// ---------------- device scratch (no allocation allowed) ----------------
__device__ float2             g_zpack[32u * 32768u];   // [s][n]  d-pair-major z
__device__ float2             g_epack[32u * 8192u];    // [s][k]  d-pair-major emb
__device__ float              g_bias[K_CODE];          // 0.5*||e_k||^2
__device__ unsigned long long g_keys[N_TOK];
__device__ int                g_idx[N_TOK];
__device__ int                g_counts[K_CODE];
__device__ float              g_sumw[K_CODE * D_DIM];
__device__ float              g_cs[K_CODE];
__device__ float              g_cssum;
__device__ float              g_loss;

// ---------------- helpers ----------------
__device__ __forceinline__ unsigned long long pack2(float x, float y) {
    float2 t = make_float2(x, y);
    unsigned long long r;
    memcpy(&r, &t, 8);
    return r;
}
__device__ __forceinline__ float2 unpack2(unsigned long long v) {
    float2 t;
    memcpy(&t, &v, 8);
    return t;
}
__device__ __forceinline__ unsigned orderf(float f) {
    unsigned u = __float_as_uint(f);
    return (u & 0x80000000u) ? ~u : (u | 0x80000000u);
}
__device__ __forceinline__ void cp16(void* dst, const void* src) {
    unsigned sa = (unsigned)__cvta_generic_to_shared(dst);
    asm volatile("cp.async.cg.shared.global [%0], [%1], 16;" :: "r"(sa), "l"(src));
}
__device__ __forceinline__ void block_atomic_add(float v, float* target) {
    #pragma unroll
    for (int m = 16; m >= 1; m >>= 1) v += __shfl_xor_sync(0xffffffffu, v, m);
    __shared__ float red[8];
    int w = threadIdx.x >> 5;
    if ((threadIdx.x & 31) == 0) red[w] = v;
    __syncthreads();
    if (threadIdx.x == 0) {
        float s = 0.f;
        #pragma unroll
        for (int i = 0; i < 8; i++) s += red[i];
        atomicAdd(target, s);
    }
}

// ---------------- K0: zero scratch ----------------
__global__ void k_zero() {
    int gid = blockIdx.x * 256 + threadIdx.x;   // 524288 threads
    g_sumw[gid] = 0.f;
    if (gid < N_TOK)  g_keys[gid]   = 0ull;
    if (gid < K_CODE) g_counts[gid] = 0;
    if (gid == 0) { g_cssum = 0.f; g_loss = 0.f; }
}

// ---------------- Kp: pack codebook + half-norms ----------------
__global__ void k_epack(const float* __restrict__ emb) {
    int k = blockIdx.x * 256 + threadIdx.x;     // 8192 threads
    const float4* ep = reinterpret_cast<const float4*>(emb + (size_t)k * D_DIM);
    float nrm = 0.f;
    #pragma unroll
    for (int s4 = 0; s4 < 16; s4++) {
        float4 v = ep[s4];
        nrm += v.x * v.x + v.y * v.y + v.z * v.z + v.w * v.w;
        g_epack[(2 * s4)     * K_CODE + k] = make_float2(v.x, v.y);
        g_epack[(2 * s4 + 1) * K_CODE + k] = make_float2(v.z, v.w);
    }
    g_bias[k] = 0.5f * nrm;
}

// ---------------- Kt: transpose/pack z (NCHW -> [s][n] float2) ----------------
__global__ void k_zpack(const float* __restrict__ z) {
    int gid = blockIdx.x * 256 + threadIdx.x;   // 1048576 threads
    int s = gid >> 15;
    int n = gid & 32767;
    int b = n >> 10, hw = n & 1023;
    const float* zp = z + (size_t)b * 65536 + (size_t)(2 * s) * 1024 + hw;
    g_zpack[s * 32768 + n] = make_float2(zp[0], zp[1024]);
}

// ---------------- K2: main fused GEMM + argmax, f32x2 packed FMA ----------------
// grid 2048 = 512 token tiles (64 tokens) x 4 K-splits; 256 threads; 80KB smem;
// 2 CTAs/SM. Warp w owns tokens [8w,8w+8); lane l owns codes {2l,2l+1,64+2l,65+2l}
// of each 128-code chunk -> E loads are 2 coalesced LDS.128, Z loads are 4
// broadcast LDS.128 (minimal crossbar traffic).
__global__ void __launch_bounds__(256, 2) k_main() {
    extern __shared__ float2 smem[];
    float2* Zs = smem;            // [32][64]
    float2* Es = smem + 2048;     // double buffer [2][32][128]

    const int tid  = threadIdx.x;
    const int lane = tid & 31;
    const int w    = tid >> 5;
    const int tile_m = blockIdx.x & 511;
    const int ks     = blockIdx.x >> 9;
    const int m0 = tile_m << 6;   // 64 tokens per block
    const int c0 = ks << 11;      // 2048 codes per K-split
    const int tok0 = w << 3;      // warp's first local token

    // load Z tile (stays for whole kernel): 32x64 float2 = 1024 float4
    #pragma unroll
    for (int r = 0; r < 4; r++) {
        int q = tid + (r << 8);
        int s = q >> 5, c4 = q & 31;
        *reinterpret_cast<float4*>(&Zs[s * 64 + c4 * 2]) =
            *reinterpret_cast<const float4*>(&g_zpack[s * 32768 + m0 + c4 * 2]);
    }
    // prologue: E tile 0 (32x128 float2 = 2048 float4)
    #pragma unroll
    for (int r = 0; r < 8; r++) {
        int q = tid + (r << 8);
        int s = q >> 6, c4 = q & 63;
        cp16(&Es[s * 128 + c4 * 2], &g_epack[s * 8192 + c0 + c4 * 2]);
    }
    asm volatile("cp.async.commit_group;");

    float bs[8]; int bi[8];
    #pragma unroll
    for (int i = 0; i < 8; i++) { bs[i] = -3.4e38f; bi[i] = 0; }

    for (int t = 0; t < 16; ++t) {
        const int buf = t & 1;
        if (t + 1 < 16) {
            int nb = (t + 1) & 1;
            int cb2 = c0 + ((t + 1) << 7);
            #pragma unroll
            for (int r = 0; r < 8; r++) {
                int q = tid + (r << 8);
                int s = q >> 6, c4 = q & 63;
                cp16(&Es[nb * 4096 + s * 128 + c4 * 2], &g_epack[s * 8192 + cb2 + c4 * 2]);
            }
            asm volatile("cp.async.commit_group;");
            asm volatile("cp.async.wait_group 1;");
        } else {
            asm volatile("cp.async.wait_group 0;");
        }
        __syncthreads();

        const int cb = c0 + (t << 7);
        // bias for this thread's 4 codes (contiguous pairs -> 2x LDG.64)
        float2 b01 = *reinterpret_cast<const float2*>(&g_bias[cb + 2 * lane]);
        float2 b23 = *reinterpret_cast<const float2*>(&g_bias[cb + 64 + 2 * lane]);

        unsigned long long acc[8][4];
        {
            unsigned long long iv0 = pack2(-b01.x, 0.f);
            unsigned long long iv1 = pack2(-b01.y, 0.f);
            unsigned long long iv2 = pack2(-b23.x, 0.f);
            unsigned long long iv3 = pack2(-b23.y, 0.f);
            #pragma unroll
            for (int i = 0; i < 8; i++) {
                acc[i][0] = iv0; acc[i][1] = iv1; acc[i][2] = iv2; acc[i][3] = iv3;
            }
        }
        const float2* Eb = Es + buf * 4096;
        #pragma unroll 1
        for (int s = 0; s < 32; ++s) {
            ulonglong2 e01 = *reinterpret_cast<const ulonglong2*>(&Eb[s * 128 + 2 * lane]);
            ulonglong2 e23 = *reinterpret_cast<const ulonglong2*>(&Eb[s * 128 + 64 + 2 * lane]);
            ulonglong2 z01 = *reinterpret_cast<const ulonglong2*>(&Zs[s * 64 + tok0]);
            ulonglong2 z23 = *reinterpret_cast<const ulonglong2*>(&Zs[s * 64 + tok0 + 2]);
            ulonglong2 z45 = *reinterpret_cast<const ulonglong2*>(&Zs[s * 64 + tok0 + 4]);
            ulonglong2 z67 = *reinterpret_cast<const ulonglong2*>(&Zs[s * 64 + tok0 + 6]);
            unsigned long long er[4] = { e01.x, e01.y, e23.x, e23.y };
            unsigned long long zr[8] = { z01.x, z01.y, z23.x, z23.y,
                                         z45.x, z45.y, z67.x, z67.y };
            #pragma unroll
            for (int i = 0; i < 8; i++)
                #pragma unroll
                for (int j = 0; j < 4; j++)
                    asm("fma.rn.f32x2 %0, %1, %2, %0;" : "+l"(acc[i][j]) : "l"(zr[i]), "l"(er[j]));
        }
        // running per-thread argmax (codes visited in increasing order; strict >
        // keeps the first/lowest-index winner, matching jnp.argmin)
        #pragma unroll
        for (int i = 0; i < 8; i++)
            #pragma unroll
            for (int j = 0; j < 4; j++) {
                float2 v = unpack2(acc[i][j]);
                float sc = v.x + v.y;                 // dot - 0.5||e||^2
                int code = cb + ((j >> 1) << 6) + 2 * lane + (j & 1);
                if (sc > bs[i]) { bs[i] = sc; bi[i] = code; }
            }
        __syncthreads();
    }

    // cross-lane argmax per token, then merge across K-splits
    #pragma unroll
    for (int i = 0; i < 8; i++) {
        float s = bs[i]; int c = bi[i];
        #pragma unroll
        for (int m = 16; m >= 1; m >>= 1) {
            float os = __shfl_xor_sync(0xffffffffu, s, m);
            int   oc = __shfl_xor_sync(0xffffffffu, c, m);
            if (os > s || (os == s && oc < c)) { s = os; c = oc; }
        }
        if (lane == 0) {
            int token = m0 + tok0 + i;
            unsigned long long key =
                ((unsigned long long)orderf(s) << 32) | (unsigned)(8191 - c);
            atomicMax(&g_keys[token], key);
        }
    }
}

// ---------------- K2b: decode argmax, counts + segment-sum of z ----------------
__global__ void k_finalize(float* __restrict__ out) {
    int n = blockIdx.x * 256 + threadIdx.x;     // 32768 threads
    unsigned long long key = g_keys[n];
    int code = 8191 - (int)(unsigned)(key & 0xffffffffu);
    g_idx[n] = code;
    out[IDX_OFF + n] = (float)code;
    atomicAdd(&g_counts[code], 1);
    float* sw = g_sumw + (size_t)code * D_DIM;
    #pragma unroll
    for (int s = 0; s < 32; s++) {
        float2 v = g_zpack[s * 32768 + n];
        atomicAdd(&sw[2 * s],     v.x);
        atomicAdd(&sw[2 * s + 1], v.y);
    }
}

// ---------------- K3: gather z_q (NCHW) + commitment-loss reduction ----------------
__global__ void k_gather(const float* __restrict__ z, const float* __restrict__ emb,
                         float* __restrict__ out) {
    int gid = blockIdx.x * 256 + threadIdx.x;   // 2097152 threads
    int b = gid >> 16, c = (gid >> 10) & 63, hw = gid & 1023;
    int n = (b << 10) | hw;
    int code = g_idx[n];
    float q  = __ldg(&emb[(size_t)code * D_DIM + c]);
    float zv = z[gid];
    float d  = q - zv;
    out[ZQ_OFF + gid] = zv + d;                 // straight-through: z + (zq - z)
    block_atomic_add(d * d, &g_loss);
}

// ---------------- K4a: cs = decay*cs_in + (1-decay)*counts ; sum ----------------
__global__ void k_cs(const float* __restrict__ cs_in) {
    int k = blockIdx.x * 256 + threadIdx.x;     // 8192 threads
    float c = DECAYF * cs_in[k] + OMDF * (float)g_counts[k];
    g_cs[k] = c;
    block_atomic_add(c, &g_cssum);
}

// ---------------- K4b: cs_norm, ema_w_out, emb_out, loss write ----------------
__global__ void k_out(const float* __restrict__ ema_w, float* __restrict__ out) {
    int gid = blockIdx.x * 256 + threadIdx.x;   // 524288 threads
    int k = gid >> 6, d = gid & 63;
    float denom = g_cssum + KEPSF;
    float cn = (g_cs[k] + EPSF) / denom;
    float ew = DECAYF * ema_w[gid] + OMDF * g_sumw[gid];
    out[EMA_OFF + gid] = ew;
    out[EMB_OFF + gid] = ew / cn;
    if (d == 0)   out[CSN_OFF + k] = cn;
    if (gid == 0) out[LOSS_OFF] = BETAF * g_loss * (1.0f / 2097152.0f);
}

// ---------------- launch ----------------
extern "C" void kernel_launch(void* const* d_in, const int* in_sizes, int n_in,
                              void* d_out, int out_size) {
    const float* z      = (const float*)d_in[0];
    const float* emb    = (const float*)d_in[1];
    const float* ema_w  = (const float*)d_in[2];
    const float* cs_in  = (const float*)d_in[3];
    float* out = (float*)d_out;

    cudaFuncSetAttribute(k_main, cudaFuncAttributeMaxDynamicSharedMemorySize, 81920);

    k_zero    <<<2048, 256>>>();
    k_epack   <<<  32, 256>>>(emb);
    k_zpack   <<<4096, 256>>>(z);
    k_main    <<<2048, 256, 81920>>>();
    k_finalize<<< 128, 256>>>(out);
    k_gather  <<<8192, 256>>>(z, emb, out);
    k_cs      <<<  32, 256>>>(cs_in);
    k_out     <<<2048, 256>>>(ema_w, out);
}